// round 5
// baseline (speedup 1.0000x reference)
#include <cuda_runtime.h>
#include <cuda_bf16.h>
#include <cstdint>

// TELIF: temporal-encoded LIF spiking neuron scan.
// tx: [T, B, N] f32, TE: [N, T] f32 -> ty: [T, B, N] f32.
//
// R5: warp-autonomous cp.async pipelines. R4 showed the limiter is the
// per-chunk iteration period (~1950 cyc vs ~1000 needed): unbatched LDS
// stalls, and the per-chunk __syncthreads convoy. Fix: per-warp private
// stage buffers (no block sync), chunk's LDS batched into registers before
// the serial chain, 6-stage ring with wait_group 4 (5 groups in flight).

#define T_STEPS 512
#define B_DIM   64
#define N_DIM   1024
#define BN      (B_DIM * N_DIM)

#define REST      0.0f
#define DECAY     0.2f
#define THRESHOLD 0.3f
#define BETA      0.02f

#define BLK       64                 // 2 warps per block
#define WARPS     (BLK / 32)
#define CHUNK     8                  // time steps per stage
#define STAGES    6
#define NCHUNK    (T_STEPS / CHUNK)  // 64
#define STAGE_F   (CHUNK * 32)       // floats per stage per array per warp (256)

__device__ float g_te_t[T_STEPS * N_DIM];  // TE transposed to [T][N]

// ---------------------------------------------------------------------------
// Transpose TE [N, T] -> g_te_t [T, N]. 32x32 tiles, padded smem.
// ---------------------------------------------------------------------------
__global__ void telif_transpose_te(const float* __restrict__ TE) {
    __shared__ float tile[32][33];
    int n0 = blockIdx.x * 32;
    int t0 = blockIdx.y * 32;
    int lx = threadIdx.x;
    int ly = threadIdx.y;

#pragma unroll
    for (int i = 0; i < 32; i += 8)
        tile[ly + i][lx] = TE[(size_t)(n0 + ly + i) * T_STEPS + (t0 + lx)];
    __syncthreads();
#pragma unroll
    for (int i = 0; i < 32; i += 8)
        g_te_t[(size_t)(t0 + ly + i) * N_DIM + (n0 + lx)] = tile[lx][ly + i];
}

// ---------------------------------------------------------------------------
// cp.async helpers
// ---------------------------------------------------------------------------
__device__ __forceinline__ void cp_async16(uint32_t smem_addr, const void* gptr) {
    asm volatile("cp.async.ca.shared.global [%0], [%1], 16;\n"
                 :: "r"(smem_addr), "l"(gptr));
}
__device__ __forceinline__ void cp_commit() {
    asm volatile("cp.async.commit_group;\n");
}
__device__ __forceinline__ void cp_wait4() {
    asm volatile("cp.async.wait_group 4;\n" ::: "memory");
}

// ---------------------------------------------------------------------------
// Main scan. One thread per (b, n). Warp-private 6-stage cp.async pipeline.
// smem: [warp][stage][step*32 + lane]
// ---------------------------------------------------------------------------
__global__ void __launch_bounds__(BLK)
telif_scan(const float* __restrict__ tx, float* __restrict__ out) {
    __shared__ __align__(16) float sm_tx[WARPS][STAGES][STAGE_F];
    __shared__ __align__(16) float sm_te[WARPS][STAGES][STAGE_F];

    const int tid  = threadIdx.x;
    const int w    = tid >> 5;
    const int lane = tid & 31;
    const int base = blockIdx.x * BLK + w * 32;   // warp's first (b*N+n) lane
    const int idx  = base + lane;
    const int n0   = base & (N_DIM - 1);          // warp's first n

    const float* txw = tx + base;                 // warp row base
    const float* tew = g_te_t + n0;
    float*       op  = out + idx;

    // cp.async split: k = lane + j*32 (j=0,1) -> step s = k>>3, 16B segment
    // seg = (k&7)*4 floats. Each 8-lane group copies one contiguous 128B row.
    auto issue = [&](int c) {
        const int buf = c % STAGES;
        const float* stx = txw + (size_t)(c * CHUNK) * BN;
        const float* ste = tew + (size_t)(c * CHUNK) * N_DIM;
        uint32_t sx = (uint32_t)__cvta_generic_to_shared(&sm_tx[w][buf][0]);
        uint32_t se = (uint32_t)__cvta_generic_to_shared(&sm_te[w][buf][0]);
#pragma unroll
        for (int j = 0; j < 2; j++) {
            int k    = lane + j * 32;
            int s    = k >> 3;
            int seg  = (k & 7) * 4;            // float offset within row
            int soff = (s * 32 + seg) * 4;     // byte offset in stage
            cp_async16(sx + soff, stx + (size_t)s * BN + seg);
            cp_async16(se + soff, ste + (size_t)s * N_DIM + seg);
        }
    };

    // Prologue: fill 5 stages.
#pragma unroll
    for (int c = 0; c < STAGES - 1; c++) {
        issue(c);
        cp_commit();
    }

    float v  = REST;
    float y  = 0.0f;
    float th = THRESHOLD;

    float* opc = op;   // advances by CHUNK*BN per chunk

#pragma unroll 1
    for (int c = 0; c < NCHUNK; c++) {
        cp_wait4();        // oldest group (chunk c) complete for this thread
        __syncwarp();      // all lanes of this warp have waited -> data visible

        if (c + STAGES - 1 < NCHUNK) issue(c + STAGES - 1);
        cp_commit();       // uniform group count incl. tail

        const int buf = c % STAGES;
        const float* ltx = &sm_tx[w][buf][lane];
        const float* lte = &sm_te[w][buf][lane];

        // Batched LDS: all 16 loads independent, issued before the chain.
        float xr[CHUNK], tr[CHUNK];
#pragma unroll
        for (int s = 0; s < CHUNK; s++) {
            xr[s] = ltx[s * 32];
            tr[s] = lte[s * 32];
        }

#pragma unroll
        for (int s = 0; s < CHUNK; s++) {
            th = th + v * tr[s] - (th - THRESHOLD) * BETA;
            v  = v * DECAY * (1.0f - y) + xr[s];
            y  = (v > th) ? 1.0f : 0.0f;
            opc[(size_t)s * BN] = y;
        }
        opc += (size_t)CHUNK * BN;

        __syncwarp();      // lanes done reading buf before it is re-issued
    }
}

// ---------------------------------------------------------------------------
// Launch
// ---------------------------------------------------------------------------
extern "C" void kernel_launch(void* const* d_in, const int* in_sizes, int n_in,
                              void* d_out, int out_size) {
    const float* tx = (const float*)d_in[0];   // [T, B, N]
    const float* TE = (const float*)d_in[1];   // [N, T]
    float* out = (float*)d_out;                // [T, B, N]

    (void)in_sizes; (void)n_in; (void)out_size;

    dim3 tb(32, 8);
    dim3 tg(N_DIM / 32, T_STEPS / 32);
    telif_transpose_te<<<tg, tb>>>(TE);

    telif_scan<<<BN / BLK, BLK>>>(tx, out);
}